// round 1
// baseline (speedup 1.0000x reference)
#include <cuda_runtime.h>
#include <math.h>

#define BN   4
#define VN   256
#define C1N  64
#define C2N  32
#define H0N  128
#define H2N  256

// ---------------- scratch (__device__ globals; no allocations allowed) ------
__device__ float g_A [BN*VN*H0N];   // per-node A_i  = x_i @ (W1a - W1b) + b1
__device__ float g_Bv[BN*VN*H0N];   // per-node B_j  = x_j @ W1b
__device__ float g_x1[BN*VN*H0N];   // edgeconv1 output
__device__ float g_x2[BN*VN*H0N];   // edgeconv2 output
__device__ float g_P [BN*VN*H2N];   // pair: x_j @ W3[0:128]
__device__ float g_Q [BN*VN*H2N];   // pair: x_i @ W3[128:256]

// ---------------------------------------------------------------------------
// prep_node: A[b,i,h] = b1[h] + sum_c x[c]*(W1[c,h]-W1[C+c,h]);
//            B[b,i,h] =          sum_c x[c]*W1[C+c,h]
// grid = B*V blocks, 128 threads
template<int C>
__global__ void prep_node_kernel(const float* __restrict__ x,
                                 const float* __restrict__ W1,   // (2C+32,128)
                                 const float* __restrict__ b1,
                                 float* __restrict__ A,
                                 float* __restrict__ Bout)
{
    __shared__ float sx[C];
    const int bi = blockIdx.x;
    const int h  = threadIdx.x;
    for (int c = h; c < C; c += 128) sx[c] = x[(size_t)bi * C + c];
    __syncthreads();
    float accA = b1[h], accB = 0.f;
#pragma unroll 4
    for (int c = 0; c < C; c++) {
        float xa = sx[c];
        float wa = W1[c * 128 + h];
        float wb = W1[(C + c) * 128 + h];
        accA += xa * (wa - wb);
        accB += xa * wb;
    }
    A   [(size_t)bi * 128 + h] = accA;
    Bout[(size_t)bi * 128 + h] = accB;
}

// ---------------------------------------------------------------------------
// Fused edgeconv: per CTA (b,i):
//   for each j-tile (64): h1 = relu(A_i + B_j + e_ij @ W1e)   (layer 1, rank-32)
//                         h2 = relu(h1 @ W2 + b2)             (64x128x128 GEMM)
//                         masked max-accumulate over adjacent j (h2 >= 0, so
//                         init 0 reproduces the -1e9/where semantics exactly)
// 256 threads, dynamic smem ~157 KB, 1 CTA/SM.
__global__ __launch_bounds__(256, 1)
void fused_ec_kernel(const int*   __restrict__ adj,
                     const float* __restrict__ e,       // (B,V,V,32)
                     const float* __restrict__ A,
                     const float* __restrict__ Bnode,
                     const float* __restrict__ W1e,     // (32,128)
                     const float* __restrict__ W2,      // (128,128)
                     const float* __restrict__ b2,
                     float* __restrict__ xout)          // (B*V,128)
{
    extern __shared__ float smem[];
    float* sW2  = smem;                    // 128*128 = 16384
    float* sW1e = sW2  + 128 * 128;        // 32*128  =  4096
    float* sA   = sW1e + 32 * 128;         // 128
    float* sb2  = sA   + 128;              // 128
    float* sBn  = sb2  + 128;              // 64*128  =  8192
    float* sE   = sBn  + 64 * 128;         // 64*32   =  2048
    float* sH1  = sE   + 64 * 32;          // 128*65  =  8320 (padded, k-major)
    int*   sAdj = (int*)(sH1 + 128 * 65);  // 64 ints

    const int tid = threadIdx.x;
    const int bi  = blockIdx.x;            // b*V + i
    const int b   = bi >> 8;

    // stage W2, W1e, A row, b2
    {
        const float4* src = (const float4*)W2;
        float4* dst = (float4*)sW2;
        for (int u = tid; u < 128 * 128 / 4; u += 256) dst[u] = src[u];
        src = (const float4*)W1e; dst = (float4*)sW1e;
        for (int u = tid; u < 32 * 128 / 4; u += 256) dst[u] = src[u];
        if (tid < 128) { sA[tid] = A[(size_t)bi * 128 + tid]; sb2[tid] = b2[tid]; }
    }
    __syncthreads();

    const int h     = tid & 127;   // layer-1 mapping
    const int jhalf = tid >> 7;
    const float a_h = sA[h];

    const int tx = tid & 15;       // GEMM: n = tx*8 .. +7
    const int ty = tid >> 4;       //        m = ty*4 .. +3

    float pmax[8];
#pragma unroll
    for (int p = 0; p < 8; p++) pmax[p] = 0.0f;

    for (int j0 = 0; j0 < 256; j0 += 64) {
        __syncthreads();  // prior tile's epilogue (sAdj) must finish before restage

        // stage B-node tile, e tile, adjacency row segment
        {
            const float4* src = (const float4*)(Bnode + ((size_t)(b * 256 + j0)) * 128);
            float4* dst = (float4*)sBn;
            for (int u = tid; u < 64 * 128 / 4; u += 256) dst[u] = src[u];
            const float4* es = (const float4*)(e + ((size_t)bi * 256 + j0) * 32);
            float4* ed = (float4*)sE;
            for (int u = tid; u < 64 * 32 / 4; u += 256) ed[u] = es[u];
            if (tid < 64) sAdj[tid] = adj[(size_t)bi * 256 + j0 + tid];
        }
        __syncthreads();

        // layer 1 -> sH1[k=h][m=jj], padded stride 65 (conflict-free stores)
        {
            float w1e[32];
#pragma unroll
            for (int c = 0; c < 32; c++) w1e[c] = sW1e[c * 128 + h];
            for (int jj = jhalf; jj < 64; jj += 2) {
                float v = a_h + sBn[jj * 128 + h];
                const float4* ee = (const float4*)(sE + jj * 32);
#pragma unroll
                for (int c4 = 0; c4 < 8; c4++) {
                    float4 ev = ee[c4];
                    v += ev.x * w1e[c4 * 4 + 0];
                    v += ev.y * w1e[c4 * 4 + 1];
                    v += ev.z * w1e[c4 * 4 + 2];
                    v += ev.w * w1e[c4 * 4 + 3];
                }
                sH1[h * 65 + jj] = fmaxf(v, 0.0f);
            }
        }
        __syncthreads();

        // GEMM: out[m][n] = sum_k sH1[k][m] * sW2[k][n]  (64x128x128)
        float acc[4][8];
#pragma unroll
        for (int q = 0; q < 4; q++)
#pragma unroll
            for (int p = 0; p < 8; p++) acc[q][p] = 0.f;

#pragma unroll 4
        for (int k = 0; k < 128; k++) {
            float a0 = sH1[k * 65 + ty * 4 + 0];
            float a1 = sH1[k * 65 + ty * 4 + 1];
            float a2 = sH1[k * 65 + ty * 4 + 2];
            float a3 = sH1[k * 65 + ty * 4 + 3];
            const float4* wr = (const float4*)(sW2 + k * 128 + tx * 8);
            float4 w0 = wr[0];
            float4 w1 = wr[1];
            float bb[8] = {w0.x, w0.y, w0.z, w0.w, w1.x, w1.y, w1.z, w1.w};
#pragma unroll
            for (int p = 0; p < 8; p++) {
                acc[0][p] += a0 * bb[p];
                acc[1][p] += a1 * bb[p];
                acc[2][p] += a2 * bb[p];
                acc[3][p] += a3 * bb[p];
            }
        }

        // epilogue: bias + relu + adjacency-masked max
#pragma unroll
        for (int q = 0; q < 4; q++) {
            int m = ty * 4 + q;
            if (sAdj[m] > 0) {
#pragma unroll
                for (int p = 0; p < 8; p++) {
                    float v = fmaxf(acc[q][p] + sb2[tx * 8 + p], 0.0f);
                    pmax[p] = fmaxf(pmax[p], v);
                }
            }
        }
    }

    // cross-thread max over the 16 ty-groups
    __syncthreads();
    float* red = sBn;  // reuse (16*128 floats)
#pragma unroll
    for (int p = 0; p < 8; p++) red[ty * 128 + tx * 8 + p] = pmax[p];
    __syncthreads();
    if (tid < 128) {
        float v = red[tid];
#pragma unroll
        for (int t = 1; t < 16; t++) v = fmaxf(v, red[t * 128 + tid]);
        xout[(size_t)bi * 128 + tid] = v;
    }
}

// ---------------------------------------------------------------------------
// pair prep: P[bi,h] = x[bi]@W3[0:128,h]; Q[bi,h] = x[bi]@W3[128:256,h]
__global__ void pair_prep_kernel(const float* __restrict__ x,    // (B*V,128)
                                 const float* __restrict__ W3,   // (256,256)
                                 float* __restrict__ P,
                                 float* __restrict__ Q)
{
    __shared__ float sx[128];
    const int bi = blockIdx.x;
    const int h  = threadIdx.x;      // 256 threads
    if (h < 128) sx[h] = x[(size_t)bi * 128 + h];
    __syncthreads();
    float p = 0.f, q = 0.f;
#pragma unroll 4
    for (int c = 0; c < 128; c++) {
        float xa = sx[c];
        p += xa * W3[c * 256 + h];
        q += xa * W3[(128 + c) * 256 + h];
    }
    P[(size_t)bi * 256 + h] = p;
    Q[(size_t)bi * 256 + h] = q;
}

// ---------------------------------------------------------------------------
// final: out[b,i,j] = sigmoid(out_b + sum_h relu(P[b,j,h]+Q[b,i,h]+b3[h])*oW[h])
__global__ void pair_final_kernel(const float* __restrict__ P,
                                  const float* __restrict__ Q,
                                  const float* __restrict__ b3,
                                  const float* __restrict__ oW,  // (256,1)
                                  const float* __restrict__ ob,  // (1,)
                                  float* __restrict__ out)       // (B,V,V)
{
    __shared__ float sQ[256], sW[256];
    const int bi  = blockIdx.x;   // b*V + i
    const int b   = bi >> 8;
    const int tid = threadIdx.x;  // 256
    sQ[tid] = Q[(size_t)bi * 256 + tid] + b3[tid];
    sW[tid] = oW[tid];
    __syncthreads();
    const float outb = ob[0];
    const int w = tid >> 5, lane = tid & 31;
    for (int j = w; j < 256; j += 8) {
        const float* pr = P + (size_t)(b * 256 + j) * 256;
        float s = 0.f;
#pragma unroll
        for (int q = 0; q < 8; q++) {
            int hh = q * 32 + lane;
            float t = fmaxf(pr[hh] + sQ[hh], 0.f);
            s += t * sW[hh];
        }
#pragma unroll
        for (int off = 16; off > 0; off >>= 1)
            s += __shfl_xor_sync(0xffffffffu, s, off);
        if (lane == 0) {
            float z = s + outb;
            out[(size_t)bi * 256 + j] = 1.0f / (1.0f + expf(-z));
        }
    }
}

// ---------------------------------------------------------------------------
extern "C" void kernel_launch(void* const* d_in, const int* in_sizes, int n_in,
                              void* d_out, int out_size)
{
    const int*   adj   = (const int*)  d_in[0];
    const float* x0    = (const float*)d_in[1];
    const float* e     = (const float*)d_in[2];
    const float* ec1W1 = (const float*)d_in[3];
    const float* ec1b1 = (const float*)d_in[4];
    const float* ec1W2 = (const float*)d_in[5];
    const float* ec1b2 = (const float*)d_in[6];
    const float* ec2W1 = (const float*)d_in[7];
    const float* ec2b1 = (const float*)d_in[8];
    const float* ec2W2 = (const float*)d_in[9];
    const float* ec2b2 = (const float*)d_in[10];
    const float* h3W   = (const float*)d_in[11];
    const float* h3b   = (const float*)d_in[12];
    const float* oW    = (const float*)d_in[13];
    const float* ob    = (const float*)d_in[14];
    float* out = (float*)d_out;

    float *gA, *gB, *gx1, *gx2, *gP, *gQ;
    cudaGetSymbolAddress((void**)&gA,  g_A);
    cudaGetSymbolAddress((void**)&gB,  g_Bv);
    cudaGetSymbolAddress((void**)&gx1, g_x1);
    cudaGetSymbolAddress((void**)&gx2, g_x2);
    cudaGetSymbolAddress((void**)&gP,  g_P);
    cudaGetSymbolAddress((void**)&gQ,  g_Q);

    const int nBI = BN * VN;                     // 1024
    const size_t fused_smem = (size_t)(128*128 + 32*128 + 128 + 128
                                       + 64*128 + 64*32 + 128*65) * 4 + 64 * 4;
    cudaFuncSetAttribute(fused_ec_kernel,
                         cudaFuncAttributeMaxDynamicSharedMemorySize,
                         (int)fused_smem);

    // EdgeConvE #1
    prep_node_kernel<C1N><<<nBI, 128>>>(x0, ec1W1, ec1b1, gA, gB);
    fused_ec_kernel<<<nBI, 256, fused_smem>>>(adj, e, gA, gB,
                                              ec1W1 + 2 * C1N * H0N,
                                              ec1W2, ec1b2, gx1);
    // EdgeConvE #2
    prep_node_kernel<H0N><<<nBI, 128>>>(gx1, ec2W1, ec2b1, gA, gB);
    fused_ec_kernel<<<nBI, 256, fused_smem>>>(adj, e, gA, gB,
                                              ec2W1 + 2 * H0N * H0N,
                                              ec2W2, ec2b2, gx2);
    // pair scoring
    pair_prep_kernel <<<nBI, 256>>>(gx2, h3W, gP, gQ);
    pair_final_kernel<<<nBI, 256>>>(gP, gQ, h3b, oW, ob, out);
}

// round 4
// speedup vs baseline: 2.9166x; 2.9166x over previous
#include <cuda_runtime.h>
#include <math.h>
#include <stdint.h>

#define BN   4
#define VN   256
#define C1N  64
#define C2N  32
#define H0N  128
#define H2N  256

// ---------------- scratch ----------------
__device__ float g_A [BN*VN*H0N];
__device__ float g_Bv[BN*VN*H0N];
__device__ float g_x1[BN*VN*H0N];
__device__ float g_x2[BN*VN*H0N];
__device__ float g_P [BN*VN*H2N];
__device__ float g_Q [BN*VN*H2N];

__device__ __forceinline__ uint32_t f32_to_tf32(float x) {
    uint32_t r;
    asm("cvt.rna.tf32.f32 %0, %1;" : "=r"(r) : "f"(x));
    return r;
}
__device__ __forceinline__ void mma_16x8x8(float* c, const uint32_t* a, const uint32_t* b) {
    asm volatile("mma.sync.aligned.m16n8k8.row.col.f32.tf32.tf32.f32 "
        "{%0,%1,%2,%3}, {%4,%5,%6,%7}, {%8,%9}, {%0,%1,%2,%3};"
        : "+f"(c[0]), "+f"(c[1]), "+f"(c[2]), "+f"(c[3])
        : "r"(a[0]), "r"(a[1]), "r"(a[2]), "r"(a[3]), "r"(b[0]), "r"(b[1]));
}

// SMEM layout in 4-byte words (padded strides: 132 and 36 -> conflict-free frags)
#define OFF_W1E 0
#define OFF_W2  (OFF_W1E + 32*132)      //  4224
#define OFF_E   (OFF_W2  + 128*132)     // 21120
#define OFF_H1  (OFF_E   + 128*36)      // 25728
#define OFF_A   (OFF_H1  + 128*132)     // 42624
#define OFF_B2  (OFF_A + 128)
#define OFF_ADJ (OFF_B2 + 128)
#define OFF_RED (OFF_ADJ + 256)
#define SMEM_WORDS (OFF_RED + 4*132)
#define SMEM_BYTES (SMEM_WORDS * 4)

// ---------------------------------------------------------------------------
template<int C>
__global__ void prep_node_kernel(const float* __restrict__ x,
                                 const float* __restrict__ W1,
                                 const float* __restrict__ b1,
                                 float* __restrict__ A,
                                 float* __restrict__ Bout)
{
    __shared__ float sx[C];
    const int bi = blockIdx.x;
    const int h  = threadIdx.x;
    for (int c = h; c < C; c += 128) sx[c] = x[(size_t)bi * C + c];
    __syncthreads();
    float accA = b1[h], accB = 0.f;
#pragma unroll 4
    for (int c = 0; c < C; c++) {
        float xa = sx[c];
        float wa = W1[c * 128 + h];
        float wb = W1[(C + c) * 128 + h];
        accA += xa * (wa - wb);
        accB += xa * wb;
    }
    A   [(size_t)bi * 128 + h] = accA;
    Bout[(size_t)bi * 128 + h] = accB;
}

// ---------------------------------------------------------------------------
// Fused edgeconv on tensor cores (mma.sync tf32). One CTA per (b,i), 256 thr.
__global__ __launch_bounds__(256, 1)
void fused_ec_mma(const int*   __restrict__ adj,
                  const float* __restrict__ e,       // (B,V,V,32)
                  const float* __restrict__ A,
                  const float* __restrict__ Bnode,
                  const float* __restrict__ W1e,     // (32,128)
                  const float* __restrict__ W2,      // (128,128)
                  const float* __restrict__ b2,
                  float* __restrict__ xout)
{
    extern __shared__ float smem[];
    uint32_t* s32 = (uint32_t*)smem;
    const int tid  = threadIdx.x;
    const int lane = tid & 31;
    const int wid  = tid >> 5;
    const int gid  = lane >> 2;      // 0..7
    const int tig  = lane & 3;       // 0..3
    const int WM   = wid & 3;        // M-group: rows WM*32..+31
    const int WN   = wid >> 2;       // N-group: cols WN*64..+63
    const int m0   = WM * 32;
    const int n0   = WN * 64;
    const int bi   = blockIdx.x;     // b*256 + i
    const int b    = bi >> 8;

    // ---- stage W1e (32x128) -> tf32, stride 132 ----
    {
        int k  = tid >> 3;
        int nb = (tid & 7) * 16;
        const float4* src = (const float4*)(W1e + k * 128 + nb);
#pragma unroll
        for (int c4 = 0; c4 < 4; c4++) {
            float4 v = src[c4];
            uint32_t* d = s32 + OFF_W1E + k * 132 + nb + c4 * 4;
            d[0] = f32_to_tf32(v.x); d[1] = f32_to_tf32(v.y);
            d[2] = f32_to_tf32(v.z); d[3] = f32_to_tf32(v.w);
        }
    }
    // ---- stage W2 (128x128) -> tf32, stride 132 ----
    {
        int k  = tid >> 1;
        int nb = (tid & 1) * 64;
        const float4* src = (const float4*)(W2 + k * 128 + nb);
#pragma unroll
        for (int c4 = 0; c4 < 16; c4++) {
            float4 v = src[c4];
            uint32_t* d = s32 + OFF_W2 + k * 132 + nb + c4 * 4;
            d[0] = f32_to_tf32(v.x); d[1] = f32_to_tf32(v.y);
            d[2] = f32_to_tf32(v.z); d[3] = f32_to_tf32(v.w);
        }
    }
    if (tid < 128) {
        smem[OFF_A  + tid] = A[(size_t)bi * 128 + tid];
        smem[OFF_B2 + tid] = b2[tid];
    }
    ((int*)(smem + OFF_ADJ))[tid] = adj[(size_t)bi * 256 + tid];

    float pmax = 0.0f;

    for (int chunk = 0; chunk < 2; chunk++) {
        const int j0 = chunk << 7;

        // ---- stage E chunk (128x32) -> tf32, stride 36 ----
        {
            int row = tid >> 1;
            int cb  = (tid & 1) * 16;
            const float4* src = (const float4*)(e + ((size_t)bi * 256 + j0 + row) * 32 + cb);
            uint32_t* d = s32 + OFF_E + row * 36 + cb;
#pragma unroll
            for (int c4 = 0; c4 < 4; c4++) {
                float4 v = src[c4];
                d[c4*4+0] = f32_to_tf32(v.x); d[c4*4+1] = f32_to_tf32(v.y);
                d[c4*4+2] = f32_to_tf32(v.z); d[c4*4+3] = f32_to_tf32(v.w);
            }
        }
        __syncthreads();

        float acc[2][8][4];
#pragma unroll
        for (int mt = 0; mt < 2; mt++)
#pragma unroll
            for (int nt = 0; nt < 8; nt++)
#pragma unroll
                for (int q = 0; q < 4; q++) acc[mt][nt][q] = 0.f;

        // ---- GEMM1: D1[j,n] = E @ W1e  (K=32) ----
#pragma unroll
        for (int ks = 0; ks < 4; ks++) {
            const int k0 = ks * 8;
            uint32_t af[2][4];
#pragma unroll
            for (int mt = 0; mt < 2; mt++) {
                const uint32_t* p = s32 + OFF_E + (m0 + mt*16 + gid) * 36 + k0 + tig;
                af[mt][0] = p[0];
                af[mt][1] = p[8 * 36];
                af[mt][2] = p[4];
                af[mt][3] = p[8 * 36 + 4];
            }
#pragma unroll
            for (int nt = 0; nt < 8; nt++) {
                const uint32_t* q = s32 + OFF_W1E + (k0 + tig) * 132 + n0 + nt*8 + gid;
                uint32_t bf[2] = { q[0], q[4 * 132] };
                mma_16x8x8(acc[0][nt], af[0], bf);
                mma_16x8x8(acc[1][nt], af[1], bf);
            }
        }

        // ---- epilogue 1: H1 = relu(D1 + A_i[n] + Bnode[j,n]) -> sH1 tf32 ----
        {
            const float* sA_ = smem + OFF_A;
#pragma unroll
            for (int mt = 0; mt < 2; mt++) {
                const int r_lo = m0 + mt*16 + gid;
                const int r_hi = r_lo + 8;
                const float2* blo = (const float2*)(Bnode + ((size_t)(b*256 + j0 + r_lo)) * 128);
                const float2* bhi = (const float2*)(Bnode + ((size_t)(b*256 + j0 + r_hi)) * 128);
#pragma unroll
                for (int nt = 0; nt < 8; nt++) {
                    const int ncol = n0 + nt*8 + 2*tig;
                    float2 bl = blo[ncol >> 1];
                    float2 bh = bhi[ncol >> 1];
                    float a0v = sA_[ncol], a1v = sA_[ncol + 1];
                    float h00 = fmaxf(acc[mt][nt][0] + a0v + bl.x, 0.f);
                    float h01 = fmaxf(acc[mt][nt][1] + a1v + bl.y, 0.f);
                    float h10 = fmaxf(acc[mt][nt][2] + a0v + bh.x, 0.f);
                    float h11 = fmaxf(acc[mt][nt][3] + a1v + bh.y, 0.f);
                    uint32_t* d0 = s32 + OFF_H1 + r_lo * 132 + ncol;
                    uint32_t* d1 = s32 + OFF_H1 + r_hi * 132 + ncol;
                    d0[0] = f32_to_tf32(h00); d0[1] = f32_to_tf32(h01);
                    d1[0] = f32_to_tf32(h10); d1[1] = f32_to_tf32(h11);
                }
            }
        }
        __syncthreads();

#pragma unroll
        for (int mt = 0; mt < 2; mt++)
#pragma unroll
            for (int nt = 0; nt < 8; nt++)
#pragma unroll
                for (int q = 0; q < 4; q++) acc[mt][nt][q] = 0.f;

        // ---- GEMM2: D2[j,n] = H1 @ W2  (K=128) ----
#pragma unroll 4
        for (int ks = 0; ks < 16; ks++) {
            const int k0 = ks * 8;
            uint32_t af[2][4];
#pragma unroll
            for (int mt = 0; mt < 2; mt++) {
                const uint32_t* p = s32 + OFF_H1 + (m0 + mt*16 + gid) * 132 + k0 + tig;
                af[mt][0] = p[0];
                af[mt][1] = p[8 * 132];
                af[mt][2] = p[4];
                af[mt][3] = p[8 * 132 + 4];
            }
#pragma unroll
            for (int nt = 0; nt < 8; nt++) {
                const uint32_t* q = s32 + OFF_W2 + (k0 + tig) * 132 + n0 + nt*8 + gid;
                uint32_t bf[2] = { q[0], q[4 * 132] };
                mma_16x8x8(acc[0][nt], af[0], bf);
                mma_16x8x8(acc[1][nt], af[1], bf);
            }
        }

        // ---- epilogue 2: bias+relu+mask, row-max -> red[WM][col] ----
        {
            const int* sAdj = (const int*)(smem + OFF_ADJ);
            const float* sb2_ = smem + OFF_B2;
            float* red = smem + OFF_RED;
            const bool k00 = sAdj[j0 + m0      + gid] > 0;
            const bool k01 = sAdj[j0 + m0 +  8 + gid] > 0;
            const bool k10 = sAdj[j0 + m0 + 16 + gid] > 0;
            const bool k11 = sAdj[j0 + m0 + 24 + gid] > 0;
#pragma unroll
            for (int nt = 0; nt < 8; nt++) {
                const int ncol = n0 + nt*8 + 2*tig;
                const float bb0 = sb2_[ncol], bb1 = sb2_[ncol + 1];
                float vA = 0.f, vB = 0.f;
                if (k00) { vA = fmaxf(vA, fmaxf(acc[0][nt][0] + bb0, 0.f));
                           vB = fmaxf(vB, fmaxf(acc[0][nt][1] + bb1, 0.f)); }
                if (k01) { vA = fmaxf(vA, fmaxf(acc[0][nt][2] + bb0, 0.f));
                           vB = fmaxf(vB, fmaxf(acc[0][nt][3] + bb1, 0.f)); }
                if (k10) { vA = fmaxf(vA, fmaxf(acc[1][nt][0] + bb0, 0.f));
                           vB = fmaxf(vB, fmaxf(acc[1][nt][1] + bb1, 0.f)); }
                if (k11) { vA = fmaxf(vA, fmaxf(acc[1][nt][2] + bb0, 0.f));
                           vB = fmaxf(vB, fmaxf(acc[1][nt][3] + bb1, 0.f)); }
#pragma unroll
                for (int msk = 4; msk <= 16; msk <<= 1) {
                    vA = fmaxf(vA, __shfl_xor_sync(0xffffffffu, vA, msk));
                    vB = fmaxf(vB, __shfl_xor_sync(0xffffffffu, vB, msk));
                }
                if (gid == 0) {
                    red[WM * 132 + ncol]     = vA;
                    red[WM * 132 + ncol + 1] = vB;
                }
            }
        }
        __syncthreads();
        if (tid < 128) {
            float v =       smem[OFF_RED           + tid];
            v = fmaxf(v, smem[OFF_RED + 132       + tid]);
            v = fmaxf(v, smem[OFF_RED + 2 * 132   + tid]);
            v = fmaxf(v, smem[OFF_RED + 3 * 132   + tid]);
            pmax = fmaxf(pmax, v);
        }
        __syncthreads();
    }

    if (tid < 128) xout[(size_t)bi * 128 + tid] = pmax;
}

// ---------------------------------------------------------------------------
__global__ void pair_prep_kernel(const float* __restrict__ x,
                                 const float* __restrict__ W3,
                                 float* __restrict__ P,
                                 float* __restrict__ Q)
{
    __shared__ float sx[128];
    const int bi = blockIdx.x;
    const int h  = threadIdx.x;
    if (h < 128) sx[h] = x[(size_t)bi * 128 + h];
    __syncthreads();
    float p = 0.f, q = 0.f;
#pragma unroll 4
    for (int c = 0; c < 128; c++) {
        float xa = sx[c];
        p += xa * W3[c * 256 + h];
        q += xa * W3[(128 + c) * 256 + h];
    }
    P[(size_t)bi * 256 + h] = p;
    Q[(size_t)bi * 256 + h] = q;
}

__global__ void pair_final_kernel(const float* __restrict__ P,
                                  const float* __restrict__ Q,
                                  const float* __restrict__ b3,
                                  const float* __restrict__ oW,
                                  const float* __restrict__ ob,
                                  float* __restrict__ out)
{
    __shared__ float sQ[256], sW[256];
    const int bi  = blockIdx.x;
    const int b   = bi >> 8;
    const int tid = threadIdx.x;
    sQ[tid] = Q[(size_t)bi * 256 + tid] + b3[tid];
    sW[tid] = oW[tid];
    __syncthreads();
    const float outb = ob[0];
    const int w = tid >> 5, lane = tid & 31;
    for (int j = w; j < 256; j += 8) {
        const float* pr = P + (size_t)(b * 256 + j) * 256;
        float s = 0.f;
#pragma unroll
        for (int q = 0; q < 8; q++) {
            int hh = q * 32 + lane;
            float t = fmaxf(pr[hh] + sQ[hh], 0.f);
            s += t * sW[hh];
        }
#pragma unroll
        for (int off = 16; off > 0; off >>= 1)
            s += __shfl_xor_sync(0xffffffffu, s, off);
        if (lane == 0) {
            float z = s + outb;
            out[(size_t)bi * 256 + j] = 1.0f / (1.0f + expf(-z));
        }
    }
}

// ---------------------------------------------------------------------------
extern "C" void kernel_launch(void* const* d_in, const int* in_sizes, int n_in,
                              void* d_out, int out_size)
{
    const int*   adj   = (const int*)  d_in[0];
    const float* x0    = (const float*)d_in[1];
    const float* e     = (const float*)d_in[2];
    const float* ec1W1 = (const float*)d_in[3];
    const float* ec1b1 = (const float*)d_in[4];
    const float* ec1W2 = (const float*)d_in[5];
    const float* ec1b2 = (const float*)d_in[6];
    const float* ec2W1 = (const float*)d_in[7];
    const float* ec2b1 = (const float*)d_in[8];
    const float* ec2W2 = (const float*)d_in[9];
    const float* ec2b2 = (const float*)d_in[10];
    const float* h3W   = (const float*)d_in[11];
    const float* h3b   = (const float*)d_in[12];
    const float* oW    = (const float*)d_in[13];
    const float* ob    = (const float*)d_in[14];
    float* out = (float*)d_out;

    float *gA, *gB, *gx1, *gx2, *gP, *gQ;
    cudaGetSymbolAddress((void**)&gA,  g_A);
    cudaGetSymbolAddress((void**)&gB,  g_Bv);
    cudaGetSymbolAddress((void**)&gx1, g_x1);
    cudaGetSymbolAddress((void**)&gx2, g_x2);
    cudaGetSymbolAddress((void**)&gP,  g_P);
    cudaGetSymbolAddress((void**)&gQ,  g_Q);

    const int nBI = BN * VN;  // 1024
    cudaFuncSetAttribute(fused_ec_mma,
                         cudaFuncAttributeMaxDynamicSharedMemorySize, SMEM_BYTES);

    // EdgeConvE #1
    prep_node_kernel<C1N><<<nBI, 128>>>(x0, ec1W1, ec1b1, gA, gB);
    fused_ec_mma<<<nBI, 256, SMEM_BYTES>>>(adj, e, gA, gB,
                                           ec1W1 + 2 * C1N * H0N, ec1W2, ec1b2, gx1);
    // EdgeConvE #2
    prep_node_kernel<H0N><<<nBI, 128>>>(gx1, ec2W1, ec2b1, gA, gB);
    fused_ec_mma<<<nBI, 256, SMEM_BYTES>>>(adj, e, gA, gB,
                                           ec2W1 + 2 * H0N * H0N, ec2W2, ec2b2, gx2);
    // pair scoring
    pair_prep_kernel <<<nBI, 256>>>(gx2, h3W, gP, gQ);
    pair_final_kernel<<<nBI, 256>>>(gP, gQ, h3b, oW, ob, out);
}